// round 1
// baseline (speedup 1.0000x reference)
#include <cuda_runtime.h>
#include <math.h>

#define N 16384
#define D 256
#define T 128
#define KC 16

// ---------------- scratch (static device allocations are allowed) ----------
__device__ float g_V[T * D];      // gathered token embeddings, [t][d]
__device__ float g_X[T * N];      // W = Dx@V^T, then in-place cumsum -> x_t
__device__ float g_g[T];          // g[s] = x_s . x_{T-1}
__device__ float g_lnA[D];        // layernorm(a_star)
__device__ float g_u[D];          // E @ y

// ---------------- K1: gather V[t] = token_emb[tokens[t]] -------------------
__global__ void k_gather(const float* __restrict__ temb, const int* __restrict__ toks) {
    int t = blockIdx.x, d = threadIdx.x;
    g_V[t * D + d] = temb[(size_t)toks[t] * D + d];
}

// ---------------- K2: W[t][n] = sum_d Dx[n][d] * V[t][d] -------------------
// M = T = 128 (whole), n-tile = 128, K = 256 in chunks of 16.
__global__ __launch_bounds__(256) void k_gemm_w(const float* __restrict__ Dx) {
    __shared__ float As[KC * 132];  // [kk][t]
    __shared__ float Bs[KC * 132];  // [kk][n]
    int tid = threadIdx.x;
    int tx = tid & 15, ty = tid >> 4;
    int n0 = blockIdx.x * 128;

    float acc[8][8];
#pragma unroll
    for (int i = 0; i < 8; i++)
#pragma unroll
        for (int j = 0; j < 8; j++) acc[i][j] = 0.f;

    for (int k0 = 0; k0 < D; k0 += KC) {
#pragma unroll
        for (int r = 0; r < 8; r++) {
            int idx = tid + 256 * r;      // 2048 elements
            int kk = idx & 15, t = idx >> 4;
            As[kk * 132 + t] = g_V[t * D + k0 + kk];
        }
#pragma unroll
        for (int r = 0; r < 8; r++) {
            int idx = tid + 256 * r;
            int kk = idx & 15, n = idx >> 4;
            Bs[kk * 132 + n] = Dx[(size_t)(n0 + n) * D + k0 + kk];
        }
        __syncthreads();
#pragma unroll
        for (int kk = 0; kk < KC; kk++) {
            float a[8], b[8];
#pragma unroll
            for (int i = 0; i < 8; i++) a[i] = As[kk * 132 + ty + 16 * i];
#pragma unroll
            for (int j = 0; j < 8; j++) b[j] = Bs[kk * 132 + tx + 16 * j];
#pragma unroll
            for (int i = 0; i < 8; i++)
#pragma unroll
                for (int j = 0; j < 8; j++) acc[i][j] = fmaf(a[i], b[j], acc[i][j]);
        }
        __syncthreads();
    }
#pragma unroll
    for (int i = 0; i < 8; i++) {
        int t = ty + 16 * i;
#pragma unroll
        for (int j = 0; j < 8; j++)
            g_X[(size_t)t * N + n0 + tx + 16 * j] = acc[i][j];
    }
}

// ---------------- K3: X[t][n] = cumsum_t relu(W[t][n]);  out[0..N)=x_f -----
__global__ void k_cumsum(float* __restrict__ out) {
    int n = blockIdx.x * 256 + threadIdx.x;
    float acc = 0.f;
#pragma unroll 8
    for (int t = 0; t < T; t++) {
        float w = g_X[(size_t)t * N + n];
        acc += fmaxf(w, 0.f);
        g_X[(size_t)t * N + n] = acc;
    }
    out[n] = acc;
}

// ---------------- K4: g[s] = x_s . x_{T-1} ---------------------------------
__global__ void k_dots() {
    __shared__ float red[256];
    int s = blockIdx.x, tid = threadIdx.x;
    const float* xs = &g_X[(size_t)s * N];
    const float* xl = &g_X[(size_t)(T - 1) * N];
    float p = 0.f;
    for (int n = tid; n < N; n += 256) p = fmaf(xs[n], xl[n], p);
    red[tid] = p;
    __syncthreads();
    for (int off = 128; off > 0; off >>= 1) {
        if (tid < off) red[tid] += red[tid + off];
        __syncthreads();
    }
    if (tid == 0) g_g[s] = red[0];
}

// ---------------- K5: a*[d] = sum_{s<127} 0.97^{127-s} g[s] V[s][d]; ln ----
__global__ void k_astar_ln() {
    __shared__ float gg[T];
    __shared__ float red[256];
    int tid = threadIdx.x;  // = d
    if (tid < T) {
        gg[tid] = (tid < T - 1)
                      ? (float)pow(0.97, (double)(T - 1 - tid)) * g_g[tid]
                      : 0.f;
    }
    __syncthreads();
    float a = 0.f;
    for (int s = 0; s < T - 1; s++) a = fmaf(gg[s], g_V[s * D + tid], a);
    // layernorm over D=256, unbiased std, eps added to std
    red[tid] = a;
    __syncthreads();
    for (int off = 128; off > 0; off >>= 1) {
        if (tid < off) red[tid] += red[tid + off];
        __syncthreads();
    }
    float m = red[0] * (1.f / D);
    __syncthreads();
    float c = a - m;
    red[tid] = c * c;
    __syncthreads();
    for (int off = 128; off > 0; off >>= 1) {
        if (tid < off) red[tid] += red[tid + off];
        __syncthreads();
    }
    float sd = sqrtf(red[0] / (float)(D - 1));
    g_lnA[tid] = c / (sd + 1e-6f);
}

// ---------------- K6: y[n] = relu(Dy[n,:].lnA) * max(x_f[n],0) -------------
__global__ void k_y(const float* __restrict__ Dy, float* __restrict__ out) {
    __shared__ float sa[D];
    int tid = threadIdx.x;
    sa[tid] = g_lnA[tid];
    __syncthreads();
    int warp = tid >> 5, lane = tid & 31;
    int n = blockIdx.x * 8 + warp;
    const float* row = &Dy[(size_t)n * D];
    float s = 0.f;
#pragma unroll
    for (int d = lane; d < D; d += 32) s = fmaf(row[d], sa[d], s);
#pragma unroll
    for (int off = 16; off > 0; off >>= 1) s += __shfl_down_sync(0xffffffffu, s, off);
    if (lane == 0) {
        float y = fmaxf(s, 0.f) * fmaxf(out[n], 0.f);  // out[n] = x_f[n]
        out[N + n] = y;
    }
}

// ---------------- K7: u[d] = E[d,:] . y ------------------------------------
__global__ void k_u(const float* __restrict__ E, const float* __restrict__ out) {
    __shared__ float red[256];
    int d = blockIdx.x, tid = threadIdx.x;
    const float* e = &E[(size_t)d * N];
    const float* y = &out[N];
    float s = 0.f;
    for (int n = tid; n < N; n += 256) s = fmaf(e[n], y[n], s);
    red[tid] = s;
    __syncthreads();
    for (int off = 128; off > 0; off >>= 1) {
        if (tid < off) red[tid] += red[tid + off];
        __syncthreads();
    }
    if (tid == 0) g_u[d] = red[0];
}

// ---------------- K8: v* = layernorm(u) ------------------------------------
__global__ void k_vstar(float* __restrict__ out) {
    __shared__ float red[256];
    int tid = threadIdx.x;
    float a = g_u[tid];
    red[tid] = a;
    __syncthreads();
    for (int off = 128; off > 0; off >>= 1) {
        if (tid < off) red[tid] += red[tid + off];
        __syncthreads();
    }
    float m = red[0] * (1.f / D);
    __syncthreads();
    float c = a - m;
    red[tid] = c * c;
    __syncthreads();
    for (int off = 128; off > 0; off >>= 1) {
        if (tid < off) red[tid] += red[tid + off];
        __syncthreads();
    }
    float sd = sqrtf(red[0] / (float)(D - 1));
    out[2 * N + tid] = c / (sd + 1e-6f);
}

// ---------------- K9: rho_f[d][n] = sum_s 0.97^{128-s} V[s][d] X[s][n] -----
// tile: 64 d x 128 n per block, K = 128 in chunks of 16
__global__ __launch_bounds__(256) void k_rho(float* __restrict__ out) {
    __shared__ float As[KC * 68];   // [kk][d] (64 wide + pad)
    __shared__ float Bs[KC * 132];  // [kk][n]
    __shared__ float cs[T];
    int tid = threadIdx.x;
    if (tid < T) cs[tid] = (float)pow(0.97, (double)(T - tid));
    __syncthreads();

    int tx = tid & 15, ty = tid >> 4;
    int n0 = blockIdx.x * 128;
    int d0 = blockIdx.y * 64;

    float acc[4][8];
#pragma unroll
    for (int i = 0; i < 4; i++)
#pragma unroll
        for (int j = 0; j < 8; j++) acc[i][j] = 0.f;

    for (int s0 = 0; s0 < T; s0 += KC) {
#pragma unroll
        for (int r = 0; r < 4; r++) {
            int idx = tid + 256 * r;  // 1024 elements
            int dd = idx & 63, kk = idx >> 6;
            As[kk * 68 + dd] = cs[s0 + kk] * g_V[(s0 + kk) * D + d0 + dd];
        }
#pragma unroll
        for (int r = 0; r < 8; r++) {
            int idx = tid + 256 * r;  // 2048 elements
            int nn = idx & 127, kk = idx >> 7;
            Bs[kk * 132 + nn] = g_X[(size_t)(s0 + kk) * N + n0 + nn];
        }
        __syncthreads();
#pragma unroll
        for (int kk = 0; kk < KC; kk++) {
            float a[4], b[8];
#pragma unroll
            for (int i = 0; i < 4; i++) a[i] = As[kk * 68 + ty + 16 * i];
#pragma unroll
            for (int j = 0; j < 8; j++) b[j] = Bs[kk * 132 + tx + 16 * j];
#pragma unroll
            for (int i = 0; i < 4; i++)
#pragma unroll
                for (int j = 0; j < 8; j++) acc[i][j] = fmaf(a[i], b[j], acc[i][j]);
        }
        __syncthreads();
    }
    float* rho = out + 2 * N + D;
#pragma unroll
    for (int i = 0; i < 4; i++) {
        int d = d0 + ty + 16 * i;
#pragma unroll
        for (int j = 0; j < 8; j++)
            rho[(size_t)d * N + n0 + tx + 16 * j] = acc[i][j];
    }
}

// ---------------------------------------------------------------------------
extern "C" void kernel_launch(void* const* d_in, const int* in_sizes, int n_in,
                              void* d_out, int out_size) {
    const float* E    = (const float*)d_in[0];
    const float* Dx   = (const float*)d_in[1];
    const float* Dy   = (const float*)d_in[2];
    const float* temb = (const float*)d_in[3];
    const int*   toks = (const int*)d_in[4];
    float* out = (float*)d_out;

    k_gather<<<T, D>>>(temb, toks);
    k_gemm_w<<<N / 128, 256>>>(Dx);
    k_cumsum<<<N / 256, 256>>>(out);
    k_dots<<<T, 256>>>();
    k_rho<<<dim3(N / 128, D / 64), 256>>>(out);
    k_astar_ln<<<1, D>>>();
    k_y<<<N / 8, 256>>>(Dy, out);
    k_u<<<D, 256>>>(E, out);
    k_vstar<<<1, D>>>(out);
}

// round 2
// speedup vs baseline: 1.5696x; 1.5696x over previous
#include <cuda_runtime.h>
#include <math.h>

#define N 16384
#define D 256
#define T 128
#define KC 16

typedef unsigned long long u64;

// ---------------- scratch ---------------------------------------------------
__device__ float g_V[T * D];       // gathered token embeddings, [t][d]
__device__ float g_X[T * N];       // cumsum'd x_t rows
__device__ float g_part[T * 8];    // partial dots
__device__ float g_lnA[D];
__device__ float g_u[D];

// ---------------- f32x2 helpers ---------------------------------------------
__device__ __forceinline__ u64 pack2same(float a) {
    u64 r;
    asm("mov.b64 %0, {%1, %2};" : "=l"(r) : "f"(a), "f"(a));
    return r;
}
__device__ __forceinline__ u64 fma2(u64 a, u64 b, u64 c) {
    u64 d;
    asm("fma.rn.f32x2 %0, %1, %2, %3;" : "=l"(d) : "l"(a), "l"(b), "l"(c));
    return d;
}
__device__ __forceinline__ float2 unpack2(u64 v) {
    float2 f;
    asm("mov.b64 {%0, %1}, %2;" : "=f"(f.x), "=f"(f.y) : "l"(v));
    return f;
}

// ---------------- K1: gather -------------------------------------------------
__global__ void k_gather(const float* __restrict__ temb, const int* __restrict__ toks) {
    int t = blockIdx.x, d = threadIdx.x;
    g_V[t * D + d] = temb[(size_t)toks[t] * D + d];
}

// ---------------- K2: W = Dx@V^T, fused relu+cumsum -> g_X, x_f -> out[0:N) --
// block: 128 t (all) x 128 n, 256 threads, f32x2 accumulators
__global__ __launch_bounds__(256) void k_gemm_w(const float* __restrict__ Dx,
                                                float* __restrict__ out) {
    extern __shared__ float sm[];
    float* As = sm;                 // [16][132]
    float* Bs = sm + KC * 132;      // [16][132]
    int tid = threadIdx.x;
    int tx = tid & 15, ty = tid >> 4;
    int n0 = blockIdx.x * 128;

    u64 acc[8][4];
#pragma unroll
    for (int i = 0; i < 8; i++)
#pragma unroll
        for (int j = 0; j < 4; j++) acc[i][j] = 0ull;

    for (int k0 = 0; k0 < D; k0 += KC) {
#pragma unroll
        for (int r = 0; r < 8; r++) {
            int idx = tid + 256 * r;
            int kk = idx & 15, t = idx >> 4;
            As[kk * 132 + t] = g_V[t * D + k0 + kk];
        }
#pragma unroll
        for (int r = 0; r < 8; r++) {
            int idx = tid + 256 * r;
            int kk = idx & 15, n = idx >> 4;
            Bs[kk * 132 + n] = Dx[(size_t)(n0 + n) * D + k0 + kk];
        }
        __syncthreads();
#pragma unroll
        for (int kk = 0; kk < KC; kk++) {
            u64 pa[8], pb[4];
#pragma unroll
            for (int i = 0; i < 8; i++) pa[i] = pack2same(As[kk * 132 + ty + 16 * i]);
#pragma unroll
            for (int j = 0; j < 4; j++)
                pb[j] = *(const u64*)&Bs[kk * 132 + 32 * j + 2 * tx];
#pragma unroll
            for (int i = 0; i < 8; i++)
#pragma unroll
                for (int j = 0; j < 4; j++) acc[i][j] = fma2(pa[i], pb[j], acc[i][j]);
        }
        __syncthreads();
    }

    // epilogue: relu into Xs[128][130] (aliases As/Bs — dead now)
    float* Xs = sm;
#pragma unroll
    for (int i = 0; i < 8; i++) {
        int t = ty + 16 * i;
#pragma unroll
        for (int j = 0; j < 4; j++) {
            float2 v = unpack2(acc[i][j]);
            v.x = fmaxf(v.x, 0.f);
            v.y = fmaxf(v.y, 0.f);
            *(float2*)&Xs[t * 130 + 32 * j + 2 * tx] = v;
        }
    }
    __syncthreads();
    // block-local cumsum over t; store x_t rows + x_f
    if (tid < 128) {
        int n = tid;
        float a = 0.f;
#pragma unroll 4
        for (int t = 0; t < T; t++) {
            a += Xs[t * 130 + n];
            g_X[(size_t)t * N + n0 + n] = a;
        }
        out[n0 + n] = a;
    }
}

// ---------------- K3: partial dots g_part[s][c] = x_s.x_127 over chunk c ----
__global__ void k_dots() {
    __shared__ float red[256];
    int s = blockIdx.x, c = blockIdx.y, tid = threadIdx.x;
    const float4* xs = (const float4*)&g_X[(size_t)s * N + c * 2048];
    const float4* xl = (const float4*)&g_X[(size_t)(T - 1) * N + c * 2048];
    float p = 0.f;
#pragma unroll
    for (int r = 0; r < 2; r++) {
        float4 a = xs[tid + 256 * r];
        float4 b = xl[tid + 256 * r];
        p = fmaf(a.x, b.x, p);
        p = fmaf(a.y, b.y, p);
        p = fmaf(a.z, b.z, p);
        p = fmaf(a.w, b.w, p);
    }
    red[tid] = p;
    __syncthreads();
    for (int off = 128; off > 0; off >>= 1) {
        if (tid < off) red[tid] += red[tid + off];
        __syncthreads();
    }
    if (tid == 0) g_part[s * 8 + c] = red[0];
}

// ---------------- K4: a*[d] -> layernorm -> g_lnA ----------------------------
__global__ void k_astar_ln() {
    __shared__ float gg[T];
    __shared__ float red[256];
    int tid = threadIdx.x;  // = d
    if (tid < T) {
        float s = 0.f;
#pragma unroll
        for (int c = 0; c < 8; c++) s += g_part[tid * 8 + c];
        gg[tid] = (tid < T - 1) ? (float)pow(0.97, (double)(T - 1 - tid)) * s : 0.f;
    }
    __syncthreads();
    float a = 0.f;
    for (int s = 0; s < T - 1; s++) a = fmaf(gg[s], g_V[s * D + tid], a);
    red[tid] = a;
    __syncthreads();
    for (int off = 128; off > 0; off >>= 1) {
        if (tid < off) red[tid] += red[tid + off];
        __syncthreads();
    }
    float m = red[0] * (1.f / D);
    __syncthreads();
    float c = a - m;
    red[tid] = c * c;
    __syncthreads();
    for (int off = 128; off > 0; off >>= 1) {
        if (tid < off) red[tid] += red[tid + off];
        __syncthreads();
    }
    float sd = sqrtf(red[0] / (float)(D - 1));
    g_lnA[tid] = c / (sd + 1e-6f);
}

// ---------------- K5: y[n] = relu(Dy.lnA) * relu(x_f) -> out[N:2N) ----------
__global__ void k_y(const float* __restrict__ Dy, float* __restrict__ out) {
    __shared__ float sa[D];
    int tid = threadIdx.x;
    sa[tid] = g_lnA[tid];
    __syncthreads();
    int warp = tid >> 5, lane = tid & 31;
    int n = blockIdx.x * 8 + warp;
    const float4* row = (const float4*)&Dy[(size_t)n * D];
    float s = 0.f;
#pragma unroll
    for (int r = 0; r < 2; r++) {
        float4 v = row[lane + 32 * r];
        int d = 4 * (lane + 32 * r);
        s = fmaf(v.x, sa[d], s);
        s = fmaf(v.y, sa[d + 1], s);
        s = fmaf(v.z, sa[d + 2], s);
        s = fmaf(v.w, sa[d + 3], s);
    }
#pragma unroll
    for (int off = 16; off > 0; off >>= 1) s += __shfl_down_sync(0xffffffffu, s, off);
    if (lane == 0) out[N + n] = fmaxf(s, 0.f) * fmaxf(out[n], 0.f);
}

// ---------------- K6: u[d] = E[d,:].y ---------------------------------------
__global__ void k_u(const float* __restrict__ E, const float* __restrict__ out) {
    __shared__ float red[256];
    int d = blockIdx.x, tid = threadIdx.x;
    const float4* e = (const float4*)&E[(size_t)d * N];
    const float4* y = (const float4*)&out[N];
    float s = 0.f;
#pragma unroll 4
    for (int r = 0; r < 16; r++) {
        float4 a = e[tid + 256 * r];
        float4 b = y[tid + 256 * r];
        s = fmaf(a.x, b.x, s);
        s = fmaf(a.y, b.y, s);
        s = fmaf(a.z, b.z, s);
        s = fmaf(a.w, b.w, s);
    }
    red[tid] = s;
    __syncthreads();
    for (int off = 128; off > 0; off >>= 1) {
        if (tid < off) red[tid] += red[tid + off];
        __syncthreads();
    }
    if (tid == 0) g_u[d] = red[0];
}

// ---------------- K7: v* = layernorm(u) -> out[2N:2N+D) ---------------------
__global__ void k_vstar(float* __restrict__ out) {
    __shared__ float red[256];
    int tid = threadIdx.x;
    float a = g_u[tid];
    red[tid] = a;
    __syncthreads();
    for (int off = 128; off > 0; off >>= 1) {
        if (tid < off) red[tid] += red[tid + off];
        __syncthreads();
    }
    float m = red[0] * (1.f / D);
    __syncthreads();
    float c = a - m;
    red[tid] = c * c;
    __syncthreads();
    for (int off = 128; off > 0; off >>= 1) {
        if (tid < off) red[tid] += red[tid + off];
        __syncthreads();
    }
    float sd = sqrtf(red[0] / (float)(D - 1));
    out[2 * N + tid] = c / (sd + 1e-6f);
}

// ---------------- K8: rho_f = V^T diag(c) X  (256d x 128n tile, f32x2) ------
__global__ __launch_bounds__(512) void k_rho(float* __restrict__ out) {
    __shared__ float As[KC * 260];   // [kk][d]
    __shared__ float Bs[KC * 132];   // [kk][n]
    __shared__ float cs[T];
    int tid = threadIdx.x;
    if (tid < T) cs[tid] = (float)pow(0.97, (double)(T - tid));
    __syncthreads();

    int tx = tid & 15, ty = tid >> 4;  // ty: 0..31
    int n0 = blockIdx.x * 128;

    u64 acc[8][4];
#pragma unroll
    for (int i = 0; i < 8; i++)
#pragma unroll
        for (int j = 0; j < 4; j++) acc[i][j] = 0ull;

    for (int s0 = 0; s0 < T; s0 += KC) {
#pragma unroll
        for (int r = 0; r < 8; r++) {
            int idx = tid + 512 * r;
            int d = idx & 255, kk = idx >> 8;
            As[kk * 260 + d] = cs[s0 + kk] * g_V[(s0 + kk) * D + d];
        }
#pragma unroll
        for (int r = 0; r < 4; r++) {
            int idx = tid + 512 * r;
            int n = idx & 127, kk = idx >> 7;
            Bs[kk * 132 + n] = g_X[(size_t)(s0 + kk) * N + n0 + n];
        }
        __syncthreads();
#pragma unroll
        for (int kk = 0; kk < KC; kk++) {
            u64 pa[8], pb[4];
#pragma unroll
            for (int i = 0; i < 8; i++) pa[i] = pack2same(As[kk * 260 + ty + 32 * i]);
#pragma unroll
            for (int j = 0; j < 4; j++)
                pb[j] = *(const u64*)&Bs[kk * 132 + 32 * j + 2 * tx];
#pragma unroll
            for (int i = 0; i < 8; i++)
#pragma unroll
                for (int j = 0; j < 4; j++) acc[i][j] = fma2(pa[i], pb[j], acc[i][j]);
        }
        __syncthreads();
    }
    float* rho = out + 2 * N + D;
#pragma unroll
    for (int i = 0; i < 8; i++) {
        int d = ty + 32 * i;
#pragma unroll
        for (int j = 0; j < 4; j++) {
            float2 v = unpack2(acc[i][j]);
            *(float2*)&rho[(size_t)d * N + n0 + 32 * j + 2 * tx] = v;
        }
    }
}

// ---------------------------------------------------------------------------
extern "C" void kernel_launch(void* const* d_in, const int* in_sizes, int n_in,
                              void* d_out, int out_size) {
    const float* E    = (const float*)d_in[0];
    const float* Dx   = (const float*)d_in[1];
    const float* Dy   = (const float*)d_in[2];
    const float* temb = (const float*)d_in[3];
    const int*   toks = (const int*)d_in[4];
    float* out = (float*)d_out;

    static int smem_set = 0;
    const int GEMM_SMEM = 128 * 130 * 4;  // 66560 B (Xs alias > As+Bs)
    if (!smem_set) {
        cudaFuncSetAttribute(k_gemm_w, cudaFuncAttributeMaxDynamicSharedMemorySize, GEMM_SMEM);
        smem_set = 1;
    }

    k_gather<<<T, D>>>(temb, toks);
    k_gemm_w<<<N / 128, 256, GEMM_SMEM>>>(Dx, out);
    k_dots<<<dim3(T, 8), 256>>>();
    k_rho<<<N / 128, 512>>>(out);
    k_astar_ln<<<1, D>>>();
    k_y<<<N / 8, 256>>>(Dy, out);
    k_u<<<D, 256>>>(E, out);
    k_vstar<<<1, D>>>(out);
}

// round 4
// speedup vs baseline: 2.0069x; 1.2786x over previous
#include <cuda_runtime.h>
#include <cuda_bf16.h>
#include <math.h>

#define N 16384
#define D 256
#define T 128

typedef unsigned int u32;
typedef unsigned long long u64;

// ---------------- scratch ---------------------------------------------------
__device__ float g_V[T * D];        // gathered token embeddings fp32 [t][d]
__device__ u32   g_XTh[N * 64];     // X^T hi split, bf16x2 [n][t/2]
__device__ u32   g_XTl[N * 64];     // X^T lo split
__device__ u32   g_cVh[D * 64];     // (0.97^(T-s)*V[s][d]) hi split, [d][s/2]
__device__ u32   g_cVl[D * 64];
__device__ float g_part2[128 * T];  // dot partials [block][s]
__device__ float g_lnA[D];
__device__ float g_u[D];

// ---------------- helpers ----------------------------------------------------
__device__ __forceinline__ u32 s2u(const void* p) {
    u32 a;
    asm("{ .reg .u64 t; cvta.to.shared.u64 t, %1; cvt.u32.u64 %0, t; }" : "=r"(a) : "l"(p));
    return a;
}
__device__ __forceinline__ u32 pack_bf16(float lo, float hi) {
    u32 r;
    asm("cvt.rn.bf16x2.f32 %0, %1, %2;" : "=r"(r) : "f"(hi), "f"(lo));
    return r;
}

#define LDSM_X4(r, addr)                                                        \
    asm volatile(                                                               \
        "ldmatrix.sync.aligned.m8n8.x4.shared.b16 {%0,%1,%2,%3}, [%4];"         \
        : "=r"((r)[0]), "=r"((r)[1]), "=r"((r)[2]), "=r"((r)[3])                \
        : "r"(addr))

__device__ __forceinline__ void mma16816(float* c, const u32* a, u32 b0, u32 b1) {
    asm volatile(
        "mma.sync.aligned.m16n8k16.row.col.f32.bf16.bf16.f32 "
        "{%0,%1,%2,%3}, {%4,%5,%6,%7}, {%8,%9}, {%0,%1,%2,%3};"
        : "+f"(c[0]), "+f"(c[1]), "+f"(c[2]), "+f"(c[3])
        : "r"(a[0]), "r"(a[1]), "r"(a[2]), "r"(a[3]), "r"(b0), "r"(b1));
}

// split float4 -> hi u64 (2 bf16x2) + lo u64
__device__ __forceinline__ void split4(float4 v, u64& hp, u64& lp) {
    u32 h0 = pack_bf16(v.x, v.y);
    u32 h1 = pack_bf16(v.z, v.w);
    u32 l0 = pack_bf16(v.x - __uint_as_float(h0 << 16),
                       v.y - __uint_as_float(h0 & 0xFFFF0000u));
    u32 l1 = pack_bf16(v.z - __uint_as_float(h1 << 16),
                       v.w - __uint_as_float(h1 & 0xFFFF0000u));
    hp = ((u64)h1 << 32) | h0;
    lp = ((u64)l1 << 32) | l0;
}

// ---------------- K1: gather -------------------------------------------------
__global__ void k_gather(const float* __restrict__ temb, const int* __restrict__ toks) {
    int t = blockIdx.x, d = threadIdx.x;
    g_V[t * D + d] = temb[(size_t)toks[t] * D + d];
}

// ---------------- K2: cV splits ----------------------------------------------
__global__ void k_prep_cv() {
    int d = blockIdx.x;
    int s2 = threadIdx.x;  // 64 threads: s pair
    int s0 = 2 * s2, s1 = s0 + 1;
    float c0 = (float)pow(0.97, (double)(T - s0));
    float c1 = (float)pow(0.97, (double)(T - s1));
    float a0 = c0 * g_V[s0 * D + d];
    float a1 = c1 * g_V[s1 * D + d];
    u32 h = pack_bf16(a0, a1);
    u32 l = pack_bf16(a0 - __uint_as_float(h << 16), a1 - __uint_as_float(h & 0xFFFF0000u));
    g_cVh[d * 64 + s2] = h;
    g_cVl[d * 64 + s2] = l;
}

// ---------------- K3: GEMM1 (mma.sync bf16 split) ----------------------------
// C[n][t] = sum_k Dx[n][k]*V[t][k]; epilogue: relu+cumsum, XT splits, partials.
#define PA1 36  // word pitch for [128][32w] tiles
__global__ __launch_bounds__(256) void k_gemm1(const float* __restrict__ Dx,
                                               float* __restrict__ out) {
    extern __shared__ char sm[];
    const int S_AH = 0, S_AL = 18432, S_BH = 36864, S_BL = 55296;
    int tid = threadIdx.x;
    int lane = tid & 31, wid = tid >> 5;
    int gr = lane >> 2, gc = lane & 3;
    int r8 = lane & 7, sub = lane >> 3;
    int m0 = wid * 16;
    int n0 = blockIdx.x * 128;
    u32 smb = s2u(sm);

    float acc[16][4];
#pragma unroll
    for (int i = 0; i < 16; i++)
#pragma unroll
        for (int j = 0; j < 4; j++) acc[i][j] = 0.f;

    int a_word = (m0 + r8 + (sub & 1) * 8) * PA1 + (sub >> 1) * 4;
    int b_word0 = (r8 + (sub >> 1) * 8) * PA1 + (sub & 1) * 4;

    for (int c = 0; c < 4; c++) {  // K chunks of 64
#pragma unroll
        for (int r = 0; r < 8; r++) {
            int gi = tid + 256 * r;
            int row = gi >> 4, f4 = gi & 15;
            float4 va = *(const float4*)&Dx[(size_t)(n0 + row) * D + c * 64 + f4 * 4];
            u64 hp, lp;
            split4(va, hp, lp);
            *(u64*)(sm + S_AH + row * (PA1 * 4) + f4 * 8) = hp;
            *(u64*)(sm + S_AL + row * (PA1 * 4) + f4 * 8) = lp;
            float4 vb = *(const float4*)&g_V[row * D + c * 64 + f4 * 4];
            split4(vb, hp, lp);
            *(u64*)(sm + S_BH + row * (PA1 * 4) + f4 * 8) = hp;
            *(u64*)(sm + S_BL + row * (PA1 * 4) + f4 * 8) = lp;
        }
        __syncthreads();
#pragma unroll
        for (int ks = 0; ks < 4; ks++) {
            u32 ah[4], al[4];
            LDSM_X4(ah, smb + S_AH + (a_word + ks * 8) * 4);
            LDSM_X4(al, smb + S_AL + (a_word + ks * 8) * 4);
#pragma unroll
            for (int g = 0; g < 8; g++) {
                u32 bh[4], bl[4];
                int boff = (b_word0 + g * 16 * PA1 + ks * 8) * 4;
                LDSM_X4(bh, smb + S_BH + boff);
                LDSM_X4(bl, smb + S_BL + boff);
                mma16816(acc[2 * g], ah, bh[0], bh[1]);
                mma16816(acc[2 * g + 1], ah, bh[2], bh[3]);
                mma16816(acc[2 * g], ah, bl[0], bl[1]);
                mma16816(acc[2 * g + 1], ah, bl[2], bl[3]);
                mma16816(acc[2 * g], al, bh[0], bh[1]);
                mma16816(acc[2 * g + 1], al, bh[2], bh[3]);
            }
        }
        __syncthreads();
    }

    // ---- epilogue: relu -> Xs[128][130], cumsum, splits, partials ----
    float* Xs = (float*)sm;
    float* sx = (float*)(sm + 66560);
#pragma unroll
    for (int nt = 0; nt < 16; nt++) {
        int col = nt * 8 + 2 * gc;
        float2 v0 = make_float2(fmaxf(acc[nt][0], 0.f), fmaxf(acc[nt][1], 0.f));
        float2 v1 = make_float2(fmaxf(acc[nt][2], 0.f), fmaxf(acc[nt][3], 0.f));
        *(float2*)&Xs[(m0 + gr) * 130 + col] = v0;
        *(float2*)&Xs[(m0 + 8 + gr) * 130 + col] = v1;
    }
    __syncthreads();
    if (tid < 128) {
        int n = tid;
        float a = 0.f;
#pragma unroll 8
        for (int t2 = 0; t2 < 64; t2++) {
            float2 v = *(float2*)&Xs[n * 130 + 2 * t2];
            a += v.x;
            float x0 = a;
            a += v.y;
            float x1 = a;
            *(float2*)&Xs[n * 130 + 2 * t2] = make_float2(x0, x1);
            u32 h = pack_bf16(x0, x1);
            u32 l = pack_bf16(x0 - __uint_as_float(h << 16),
                              x1 - __uint_as_float(h & 0xFFFF0000u));
            g_XTh[(size_t)(n0 + n) * 64 + t2] = h;
            g_XTl[(size_t)(n0 + n) * 64 + t2] = l;
        }
        out[n0 + n] = a;
        sx[n] = a;
    }
    __syncthreads();
    if (tid < 128) {
        int t = tid;
        float s = 0.f;
        for (int n2 = 0; n2 < 128; n2++) s = fmaf(Xs[n2 * 130 + t], sx[n2], s);
        g_part2[blockIdx.x * 128 + t] = s;
    }
}

// ---------------- K4: GEMM2 (mma.sync bf16 split) ----------------------------
// C[d][n] = sum_s cV[d][s]*XT[n][s]; coalesced float2 stores to rho[d][n].
#define PA2 68  // word pitch for [*][64w] tiles
__global__ __launch_bounds__(512) void k_gemm2(float* __restrict__ out) {
    extern __shared__ char sm[];
    const int S_AH = 0, S_AL = 69632, S_BH = 139264, S_BL = 174080;
    int tid = threadIdx.x;
    int lane = tid & 31, wid = tid >> 5;  // wid 0..15
    int gr = lane >> 2, gc = lane & 3;
    int r8 = lane & 7, sub = lane >> 3;
    int m0 = wid * 16;  // d rows
    int n0 = blockIdx.x * 128;
    u32 smb = s2u(sm);

    // stage cV [256][64w] hi/lo and XT [128][64w] hi/lo
#pragma unroll
    for (int r = 0; r < 8; r++) {
        int gi = tid + 512 * r;  // 4096 uint4
        int row = gi >> 4, j4 = gi & 15;
        *(uint4*)(sm + S_AH + row * (PA2 * 4) + j4 * 16) =
            ((const uint4*)g_cVh)[row * 16 + j4];
        *(uint4*)(sm + S_AL + row * (PA2 * 4) + j4 * 16) =
            ((const uint4*)g_cVl)[row * 16 + j4];
    }
#pragma unroll
    for (int r = 0; r < 4; r++) {
        int gi = tid + 512 * r;  // 2048 uint4
        int row = gi >> 4, j4 = gi & 15;
        *(uint4*)(sm + S_BH + row * (PA2 * 4) + j4 * 16) =
            ((const uint4*)g_XTh)[(size_t)(n0 + row) * 16 + j4];
        *(uint4*)(sm + S_BL + row * (PA2 * 4) + j4 * 16) =
            ((const uint4*)g_XTl)[(size_t)(n0 + row) * 16 + j4];
    }
    __syncthreads();

    float acc[16][4];
#pragma unroll
    for (int i = 0; i < 16; i++)
#pragma unroll
        for (int j = 0; j < 4; j++) acc[i][j] = 0.f;

    int a_word = (m0 + r8 + (sub & 1) * 8) * PA2 + (sub >> 1) * 4;
    int b_word0 = (r8 + (sub >> 1) * 8) * PA2 + (sub & 1) * 4;

#pragma unroll
    for (int ks = 0; ks < 8; ks++) {
        u32 ah[4], al[4];
        LDSM_X4(ah, smb + S_AH + (a_word + ks * 8) * 4);
        LDSM_X4(al, smb + S_AL + (a_word + ks * 8) * 4);
#pragma unroll
        for (int g = 0; g < 8; g++) {
            u32 bh[4], bl[4];
            int boff = (b_word0 + g * 16 * PA2 + ks * 8) * 4;
            LDSM_X4(bh, smb + S_BH + boff);
            LDSM_X4(bl, smb + S_BL + boff);
            mma16816(acc[2 * g], ah, bh[0], bh[1]);
            mma16816(acc[2 * g + 1], ah, bh[2], bh[3]);
            mma16816(acc[2 * g], ah, bl[0], bl[1]);
            mma16816(acc[2 * g + 1], ah, bl[2], bl[3]);
            mma16816(acc[2 * g], al, bh[0], bh[1]);
            mma16816(acc[2 * g + 1], al, bh[2], bh[3]);
        }
    }

    float* rho = out + 2 * N + D;
#pragma unroll
    for (int nt = 0; nt < 16; nt++) {
        int col = n0 + nt * 8 + 2 * gc;
        int d = m0 + gr;
        *(float2*)&rho[(size_t)d * N + col] = make_float2(acc[nt][0], acc[nt][1]);
        *(float2*)&rho[(size_t)(d + 8) * N + col] = make_float2(acc[nt][2], acc[nt][3]);
    }
}

// ---------------- K5: a*[d] -> layernorm -> g_lnA ----------------------------
__global__ void k_astar_ln() {
    __shared__ float gg[T];
    __shared__ float red[256];
    int tid = threadIdx.x;  // = d
    if (tid < T) {
        float s = 0.f;
        for (int b = 0; b < 128; b++) s += g_part2[b * 128 + tid];
        gg[tid] = (tid < T - 1) ? (float)pow(0.97, (double)(T - 1 - tid)) * s : 0.f;
    }
    __syncthreads();
    float a = 0.f;
    for (int s = 0; s < T - 1; s++) a = fmaf(gg[s], g_V[s * D + tid], a);
    red[tid] = a;
    __syncthreads();
    for (int off = 128; off > 0; off >>= 1) {
        if (tid < off) red[tid] += red[tid + off];
        __syncthreads();
    }
    float m = red[0] * (1.f / D);
    __syncthreads();
    float ctr = a - m;
    red[tid] = ctr * ctr;
    __syncthreads();
    for (int off = 128; off > 0; off >>= 1) {
        if (tid < off) red[tid] += red[tid + off];
        __syncthreads();
    }
    float sd = sqrtf(red[0] / (float)(D - 1));
    g_lnA[tid] = ctr / (sd + 1e-6f);
}

// ---------------- K6: y[n] = relu(Dy.lnA) * relu(x_f) -> out[N:2N) ----------
__global__ void k_y(const float* __restrict__ Dy, float* __restrict__ out) {
    __shared__ float sa[D];
    int tid = threadIdx.x;
    sa[tid] = g_lnA[tid];
    __syncthreads();
    int warp = tid >> 5, lane = tid & 31;
    int n = blockIdx.x * 8 + warp;
    const float4* row = (const float4*)&Dy[(size_t)n * D];
    float s = 0.f;
#pragma unroll
    for (int r = 0; r < 2; r++) {
        float4 v = row[lane + 32 * r];
        int d = 4 * (lane + 32 * r);
        s = fmaf(v.x, sa[d], s);
        s = fmaf(v.y, sa[d + 1], s);
        s = fmaf(v.z, sa[d + 2], s);
        s = fmaf(v.w, sa[d + 3], s);
    }
#pragma unroll
    for (int off = 16; off > 0; off >>= 1) s += __shfl_down_sync(0xffffffffu, s, off);
    if (lane == 0) out[N + n] = fmaxf(s, 0.f) * fmaxf(out[n], 0.f);
}

// ---------------- K7: u[d] = E[d,:].y ---------------------------------------
__global__ void k_u(const float* __restrict__ E, const float* __restrict__ out) {
    __shared__ float red[256];
    int d = blockIdx.x, tid = threadIdx.x;
    const float4* e = (const float4*)&E[(size_t)d * N];
    const float4* y = (const float4*)&out[N];
    float s = 0.f;
#pragma unroll 4
    for (int r = 0; r < 16; r++) {
        float4 a = e[tid + 256 * r];
        float4 b = y[tid + 256 * r];
        s = fmaf(a.x, b.x, s);
        s = fmaf(a.y, b.y, s);
        s = fmaf(a.z, b.z, s);
        s = fmaf(a.w, b.w, s);
    }
    red[tid] = s;
    __syncthreads();
    for (int off = 128; off > 0; off >>= 1) {
        if (tid < off) red[tid] += red[tid + off];
        __syncthreads();
    }
    if (tid == 0) g_u[d] = red[0];
}

// ---------------- K8: v* = layernorm(u) -> out[2N:2N+D) ---------------------
__global__ void k_vstar(float* __restrict__ out) {
    __shared__ float red[256];
    int tid = threadIdx.x;
    float a = g_u[tid];
    red[tid] = a;
    __syncthreads();
    for (int off = 128; off > 0; off >>= 1) {
        if (tid < off) red[tid] += red[tid + off];
        __syncthreads();
    }
    float m = red[0] * (1.f / D);
    __syncthreads();
    float c = a - m;
    red[tid] = c * c;
    __syncthreads();
    for (int off = 128; off > 0; off >>= 1) {
        if (tid < off) red[tid] += red[tid + off];
        __syncthreads();
    }
    float sd = sqrtf(red[0] / (float)(D - 1));
    out[2 * N + tid] = c / (sd + 1e-6f);
}

// ---------------------------------------------------------------------------
extern "C" void kernel_launch(void* const* d_in, const int* in_sizes, int n_in,
                              void* d_out, int out_size) {
    const float* E    = (const float*)d_in[0];
    const float* Dx   = (const float*)d_in[1];
    const float* Dy   = (const float*)d_in[2];
    const float* temb = (const float*)d_in[3];
    const int*   toks = (const int*)d_in[4];
    float* out = (float*)d_out;

    const int SM1 = 73728;   // 4 x [128][36w] tiles; epilogue Xs+sx fits under
    const int SM2 = 208896;  // cV hi/lo [256][68w] + XT hi/lo [128][68w]
    static int smem_set = 0;
    if (!smem_set) {
        cudaFuncSetAttribute(k_gemm1, cudaFuncAttributeMaxDynamicSharedMemorySize, SM1);
        cudaFuncSetAttribute(k_gemm2, cudaFuncAttributeMaxDynamicSharedMemorySize, SM2);
        smem_set = 1;
    }

    k_gather<<<T, D>>>(temb, toks);
    k_prep_cv<<<D, 64>>>();
    k_gemm1<<<N / 128, 256, SM1>>>(Dx, out);
    k_gemm2<<<N / 128, 512, SM2>>>(out);
    k_astar_ln<<<1, D>>>();
    k_y<<<N / 8, 256>>>(Dy, out);
    k_u<<<D, 256>>>(E, out);
    k_vstar<<<1, D>>>(out);
}

// round 5
// speedup vs baseline: 2.5226x; 1.2570x over previous
#include <cuda_runtime.h>
#include <cuda_bf16.h>
#include <math.h>

#define N 16384
#define D 256
#define T 128

typedef unsigned int u32;
typedef unsigned long long u64;

// ---------------- scratch ---------------------------------------------------
__device__ float g_V[T * D];        // gathered token embeddings fp32 [t][d]
__device__ u32   g_Vh[T * 128];     // V hi split bf16x2 [t][k/2]
__device__ u32   g_Vl[T * 128];     // V lo split
__device__ u32   g_XTh[N * 64];     // X^T hi split, bf16x2 [n][t/2]
__device__ u32   g_XTl[N * 64];     // X^T lo split
__device__ u32   g_cVh[D * 64];     // (0.97^(T-s)*V[s][d]) hi split, [d][s/2]
__device__ u32   g_cVl[D * 64];
__device__ float g_part2[128 * T];  // dot partials [block][s]
__device__ float g_lnA[D];
__device__ float g_u[D];

// ---------------- helpers ----------------------------------------------------
__device__ __forceinline__ u32 s2u(const void* p) {
    u32 a;
    asm("{ .reg .u64 t; cvta.to.shared.u64 t, %1; cvt.u32.u64 %0, t; }" : "=r"(a) : "l"(p));
    return a;
}
__device__ __forceinline__ u32 pack_bf16(float lo, float hi) {
    u32 r;
    asm("cvt.rn.bf16x2.f32 %0, %1, %2;" : "=r"(r) : "f"(hi), "f"(lo));
    return r;
}

#define LDSM_X4(r, addr)                                                        \
    asm volatile(                                                               \
        "ldmatrix.sync.aligned.m8n8.x4.shared.b16 {%0,%1,%2,%3}, [%4];"         \
        : "=r"((r)[0]), "=r"((r)[1]), "=r"((r)[2]), "=r"((r)[3])                \
        : "r"(addr))

__device__ __forceinline__ void mma16816(float* c, const u32* a, u32 b0, u32 b1) {
    asm volatile(
        "mma.sync.aligned.m16n8k16.row.col.f32.bf16.bf16.f32 "
        "{%0,%1,%2,%3}, {%4,%5,%6,%7}, {%8,%9}, {%0,%1,%2,%3};"
        : "+f"(c[0]), "+f"(c[1]), "+f"(c[2]), "+f"(c[3])
        : "r"(a[0]), "r"(a[1]), "r"(a[2]), "r"(a[3]), "r"(b0), "r"(b1));
}

// split float4 -> hi u64 (2 bf16x2) + lo u64
__device__ __forceinline__ void split4(float4 v, u64& hp, u64& lp) {
    u32 h0 = pack_bf16(v.x, v.y);
    u32 h1 = pack_bf16(v.z, v.w);
    u32 l0 = pack_bf16(v.x - __uint_as_float(h0 << 16),
                       v.y - __uint_as_float(h0 & 0xFFFF0000u));
    u32 l1 = pack_bf16(v.z - __uint_as_float(h1 << 16),
                       v.w - __uint_as_float(h1 & 0xFFFF0000u));
    hp = ((u64)h1 << 32) | h0;
    lp = ((u64)l1 << 32) | l0;
}

// ---------------- K1: gather + V splits --------------------------------------
__global__ __launch_bounds__(256) void k_gather_prep(const float* __restrict__ temb,
                                                     const int* __restrict__ toks) {
    int t = blockIdx.x, tid = threadIdx.x;
    g_V[t * D + tid] = temb[(size_t)toks[t] * D + tid];
    __syncthreads();
    if (tid < 128) {
        float v0 = g_V[t * D + 2 * tid];
        float v1 = g_V[t * D + 2 * tid + 1];
        u32 h = pack_bf16(v0, v1);
        u32 l = pack_bf16(v0 - __uint_as_float(h << 16),
                          v1 - __uint_as_float(h & 0xFFFF0000u));
        g_Vh[t * 128 + tid] = h;
        g_Vl[t * 128 + tid] = l;
    }
}

// ---------------- K2: cV splits ----------------------------------------------
__global__ void k_prep_cv() {
    int d = blockIdx.x;
    int s2 = threadIdx.x;  // 64 threads: s pair
    int s0 = 2 * s2, s1 = s0 + 1;
    float c0 = (float)pow(0.97, (double)(T - s0));
    float c1 = (float)pow(0.97, (double)(T - s1));
    float a0 = c0 * g_V[s0 * D + d];
    float a1 = c1 * g_V[s1 * D + d];
    u32 h = pack_bf16(a0, a1);
    u32 l = pack_bf16(a0 - __uint_as_float(h << 16), a1 - __uint_as_float(h & 0xFFFF0000u));
    g_cVh[d * 64 + s2] = h;
    g_cVl[d * 64 + s2] = l;
}

// ---------------- K3: GEMM1 (mma.sync bf16 split, Dx prefetch) ---------------
// C[n][t] = sum_k Dx[n][k]*V[t][k]; epilogue: relu+cumsum, XT splits, partials.
#define PA1 36  // word pitch for [128][32w] tiles
__global__ __launch_bounds__(256) void k_gemm1(const float* __restrict__ Dx,
                                               float* __restrict__ out) {
    extern __shared__ char sm[];
    const int S_AH = 0, S_AL = 18432, S_BH = 36864, S_BL = 55296;
    int tid = threadIdx.x;
    int lane = tid & 31, wid = tid >> 5;
    int gr = lane >> 2, gc = lane & 3;
    int r8 = lane & 7, sub = lane >> 3;
    int m0 = wid * 16;
    int n0 = blockIdx.x * 128;
    u32 smb = s2u(sm);

    float acc[16][4];
#pragma unroll
    for (int i = 0; i < 16; i++)
#pragma unroll
        for (int j = 0; j < 4; j++) acc[i][j] = 0.f;

    int a_word = (m0 + r8 + (sub & 1) * 8) * PA1 + (sub >> 1) * 4;
    int b_word0 = (r8 + (sub >> 1) * 8) * PA1 + (sub & 1) * 4;

    // prefetch chunk 0 of Dx
    float4 pa[8];
#pragma unroll
    for (int r = 0; r < 8; r++) {
        int gi = tid + 256 * r;
        int row = gi >> 4, f4 = gi & 15;
        pa[r] = *(const float4*)&Dx[(size_t)(n0 + row) * D + f4 * 4];
    }

    for (int c = 0; c < 4; c++) {  // K chunks of 64
        // stage A from prefetched regs; B direct from pre-split V (L2-hot)
#pragma unroll
        for (int r = 0; r < 8; r++) {
            int gi = tid + 256 * r;
            int row = gi >> 4, f4 = gi & 15;
            u64 hp, lp;
            split4(pa[r], hp, lp);
            *(u64*)(sm + S_AH + row * (PA1 * 4) + f4 * 8) = hp;
            *(u64*)(sm + S_AL + row * (PA1 * 4) + f4 * 8) = lp;
        }
#pragma unroll
        for (int r = 0; r < 4; r++) {
            int gi = tid + 256 * r;  // 1024 uint4 per split
            int row = gi >> 3, j4 = gi & 7;
            *(uint4*)(sm + S_BH + row * (PA1 * 4) + j4 * 16) =
                ((const uint4*)g_Vh)[row * 32 + c * 8 + j4];
            *(uint4*)(sm + S_BL + row * (PA1 * 4) + j4 * 16) =
                ((const uint4*)g_Vl)[row * 32 + c * 8 + j4];
        }
        __syncthreads();
        // prefetch next Dx chunk while MMAs run
        if (c < 3) {
#pragma unroll
            for (int r = 0; r < 8; r++) {
                int gi = tid + 256 * r;
                int row = gi >> 4, f4 = gi & 15;
                pa[r] = *(const float4*)&Dx[(size_t)(n0 + row) * D + (c + 1) * 64 + f4 * 4];
            }
        }
#pragma unroll
        for (int ks = 0; ks < 4; ks++) {
            u32 ah[4], al[4];
            LDSM_X4(ah, smb + S_AH + (a_word + ks * 8) * 4);
            LDSM_X4(al, smb + S_AL + (a_word + ks * 8) * 4);
#pragma unroll
            for (int g = 0; g < 8; g++) {
                u32 bh[4], bl[4];
                int boff = (b_word0 + g * 16 * PA1 + ks * 8) * 4;
                LDSM_X4(bh, smb + S_BH + boff);
                LDSM_X4(bl, smb + S_BL + boff);
                mma16816(acc[2 * g], ah, bh[0], bh[1]);
                mma16816(acc[2 * g + 1], ah, bh[2], bh[3]);
                mma16816(acc[2 * g], ah, bl[0], bl[1]);
                mma16816(acc[2 * g + 1], ah, bl[2], bl[3]);
                mma16816(acc[2 * g], al, bh[0], bh[1]);
                mma16816(acc[2 * g + 1], al, bh[2], bh[3]);
            }
        }
        __syncthreads();
    }

    // ---- epilogue: relu -> Xs[128][130], 2-phase cumsum, splits, partials ----
    float* Xs = (float*)sm;
    float* sx = (float*)(sm + 66560);           // [128] x_f
    float* tot = (float*)(sm + 66560 + 512);    // [128][2] half totals
#pragma unroll
    for (int nt = 0; nt < 16; nt++) {
        int col = nt * 8 + 2 * gc;
        float2 v0 = make_float2(fmaxf(acc[nt][0], 0.f), fmaxf(acc[nt][1], 0.f));
        float2 v1 = make_float2(fmaxf(acc[nt][2], 0.f), fmaxf(acc[nt][3], 0.f));
        *(float2*)&Xs[(m0 + gr) * 130 + col] = v0;
        *(float2*)&Xs[(m0 + 8 + gr) * 130 + col] = v1;
    }
    __syncthreads();
    {
        int n = tid & 127, h = tid >> 7;
        float v[64];
        float a = 0.f;
#pragma unroll
        for (int i = 0; i < 32; i++) {
            float2 p = *(float2*)&Xs[n * 130 + h * 64 + 2 * i];
            a += p.x;
            v[2 * i] = a;
            a += p.y;
            v[2 * i + 1] = a;
        }
        tot[n * 2 + h] = a;
        __syncthreads();
        float off = h ? tot[n * 2] : 0.f;
#pragma unroll
        for (int i = 0; i < 64; i++) v[i] += off;
#pragma unroll
        for (int p = 0; p < 32; p++) {
            float x0 = v[2 * p], x1 = v[2 * p + 1];
            *(float2*)&Xs[n * 130 + h * 64 + 2 * p] = make_float2(x0, x1);
            u32 hh = pack_bf16(x0, x1);
            u32 ll = pack_bf16(x0 - __uint_as_float(hh << 16),
                               x1 - __uint_as_float(hh & 0xFFFF0000u));
            g_XTh[(size_t)(n0 + n) * 64 + h * 32 + p] = hh;
            g_XTl[(size_t)(n0 + n) * 64 + h * 32 + p] = ll;
        }
        if (h == 1) {
            out[n0 + n] = v[63];
            sx[n] = v[63];
        }
    }
    __syncthreads();
    {
        int t = tid & 127, h = tid >> 7;
        float s = 0.f;
        for (int n2 = h * 64; n2 < h * 64 + 64; n2++)
            s = fmaf(Xs[n2 * 130 + t], sx[n2], s);
        tot[t * 2 + h] = s;
    }
    __syncthreads();
    if (tid < 128) g_part2[blockIdx.x * 128 + tid] = tot[tid * 2] + tot[tid * 2 + 1];
}

// ---------------- K4: GEMM2 (mma.sync bf16 split) ----------------------------
// C[d][n] = sum_s cV[d][s]*XT[n][s]; coalesced float2 stores to rho[d][n].
#define PA2 68  // word pitch for [*][64w] tiles
__global__ __launch_bounds__(512) void k_gemm2(float* __restrict__ out) {
    extern __shared__ char sm[];
    const int S_AH = 0, S_AL = 69632, S_BH = 139264, S_BL = 174080;
    int tid = threadIdx.x;
    int lane = tid & 31, wid = tid >> 5;  // wid 0..15
    int gr = lane >> 2, gc = lane & 3;
    int r8 = lane & 7, sub = lane >> 3;
    int m0 = wid * 16;  // d rows
    int n0 = blockIdx.x * 128;
    u32 smb = s2u(sm);

#pragma unroll
    for (int r = 0; r < 8; r++) {
        int gi = tid + 512 * r;  // 4096 uint4
        int row = gi >> 4, j4 = gi & 15;
        *(uint4*)(sm + S_AH + row * (PA2 * 4) + j4 * 16) =
            ((const uint4*)g_cVh)[row * 16 + j4];
        *(uint4*)(sm + S_AL + row * (PA2 * 4) + j4 * 16) =
            ((const uint4*)g_cVl)[row * 16 + j4];
    }
#pragma unroll
    for (int r = 0; r < 4; r++) {
        int gi = tid + 512 * r;  // 2048 uint4
        int row = gi >> 4, j4 = gi & 15;
        *(uint4*)(sm + S_BH + row * (PA2 * 4) + j4 * 16) =
            ((const uint4*)g_XTh)[(size_t)(n0 + row) * 16 + j4];
        *(uint4*)(sm + S_BL + row * (PA2 * 4) + j4 * 16) =
            ((const uint4*)g_XTl)[(size_t)(n0 + row) * 16 + j4];
    }
    __syncthreads();

    float acc[16][4];
#pragma unroll
    for (int i = 0; i < 16; i++)
#pragma unroll
        for (int j = 0; j < 4; j++) acc[i][j] = 0.f;

    int a_word = (m0 + r8 + (sub & 1) * 8) * PA2 + (sub >> 1) * 4;
    int b_word0 = (r8 + (sub >> 1) * 8) * PA2 + (sub & 1) * 4;

#pragma unroll
    for (int ks = 0; ks < 8; ks++) {
        u32 ah[4], al[4];
        LDSM_X4(ah, smb + S_AH + (a_word + ks * 8) * 4);
        LDSM_X4(al, smb + S_AL + (a_word + ks * 8) * 4);
#pragma unroll
        for (int g = 0; g < 8; g++) {
            u32 bh[4], bl[4];
            int boff = (b_word0 + g * 16 * PA2 + ks * 8) * 4;
            LDSM_X4(bh, smb + S_BH + boff);
            LDSM_X4(bl, smb + S_BL + boff);
            mma16816(acc[2 * g], ah, bh[0], bh[1]);
            mma16816(acc[2 * g + 1], ah, bh[2], bh[3]);
            mma16816(acc[2 * g], ah, bl[0], bl[1]);
            mma16816(acc[2 * g + 1], ah, bl[2], bl[3]);
            mma16816(acc[2 * g], al, bh[0], bh[1]);
            mma16816(acc[2 * g + 1], al, bh[2], bh[3]);
        }
    }

    float* rho = out + 2 * N + D;
#pragma unroll
    for (int nt = 0; nt < 16; nt++) {
        int col = n0 + nt * 8 + 2 * gc;
        int d = m0 + gr;
        *(float2*)&rho[(size_t)d * N + col] = make_float2(acc[nt][0], acc[nt][1]);
        *(float2*)&rho[(size_t)(d + 8) * N + col] = make_float2(acc[nt][2], acc[nt][3]);
    }
}

// ---------------- K5: a*[d] -> layernorm -> g_lnA ----------------------------
__global__ void k_astar_ln() {
    __shared__ float gg[T];
    __shared__ float red[256];
    int tid = threadIdx.x;  // = d
    if (tid < T) {
        float s = 0.f;
        for (int b = 0; b < 128; b++) s += g_part2[b * 128 + tid];
        gg[tid] = (tid < T - 1) ? (float)pow(0.97, (double)(T - 1 - tid)) * s : 0.f;
    }
    __syncthreads();
    float a = 0.f;
    for (int s = 0; s < T - 1; s++) a = fmaf(gg[s], g_V[s * D + tid], a);
    red[tid] = a;
    __syncthreads();
    for (int off = 128; off > 0; off >>= 1) {
        if (tid < off) red[tid] += red[tid + off];
        __syncthreads();
    }
    float m = red[0] * (1.f / D);
    __syncthreads();
    float ctr = a - m;
    red[tid] = ctr * ctr;
    __syncthreads();
    for (int off = 128; off > 0; off >>= 1) {
        if (tid < off) red[tid] += red[tid + off];
        __syncthreads();
    }
    float sd = sqrtf(red[0] / (float)(D - 1));
    g_lnA[tid] = ctr / (sd + 1e-6f);
}

// ---------------- K6: y[n] = relu(Dy.lnA) * relu(x_f) -> out[N:2N) ----------
__global__ void k_y(const float* __restrict__ Dy, float* __restrict__ out) {
    __shared__ float sa[D];
    int tid = threadIdx.x;
    sa[tid] = g_lnA[tid];
    __syncthreads();
    int warp = tid >> 5, lane = tid & 31;
    int n = blockIdx.x * 8 + warp;
    const float4* row = (const float4*)&Dy[(size_t)n * D];
    float s = 0.f;
#pragma unroll
    for (int r = 0; r < 2; r++) {
        float4 v = row[lane + 32 * r];
        int d = 4 * (lane + 32 * r);
        s = fmaf(v.x, sa[d], s);
        s = fmaf(v.y, sa[d + 1], s);
        s = fmaf(v.z, sa[d + 2], s);
        s = fmaf(v.w, sa[d + 3], s);
    }
#pragma unroll
    for (int off = 16; off > 0; off >>= 1) s += __shfl_down_sync(0xffffffffu, s, off);
    if (lane == 0) out[N + n] = fmaxf(s, 0.f) * fmaxf(out[n], 0.f);
}

// ---------------- K7: u[d] = E[d,:].y ---------------------------------------
__global__ void k_u(const float* __restrict__ E, const float* __restrict__ out) {
    __shared__ float red[256];
    int d = blockIdx.x, tid = threadIdx.x;
    const float4* e = (const float4*)&E[(size_t)d * N];
    const float4* y = (const float4*)&out[N];
    float s = 0.f;
#pragma unroll 4
    for (int r = 0; r < 16; r++) {
        float4 a = e[tid + 256 * r];
        float4 b = y[tid + 256 * r];
        s = fmaf(a.x, b.x, s);
        s = fmaf(a.y, b.y, s);
        s = fmaf(a.z, b.z, s);
        s = fmaf(a.w, b.w, s);
    }
    red[tid] = s;
    __syncthreads();
    for (int off = 128; off > 0; off >>= 1) {
        if (tid < off) red[tid] += red[tid + off];
        __syncthreads();
    }
    if (tid == 0) g_u[d] = red[0];
}

// ---------------- K8: v* = layernorm(u) -> out[2N:2N+D) ---------------------
__global__ void k_vstar(float* __restrict__ out) {
    __shared__ float red[256];
    int tid = threadIdx.x;
    float a = g_u[tid];
    red[tid] = a;
    __syncthreads();
    for (int off = 128; off > 0; off >>= 1) {
        if (tid < off) red[tid] += red[tid + off];
        __syncthreads();
    }
    float m = red[0] * (1.f / D);
    __syncthreads();
    float c = a - m;
    red[tid] = c * c;
    __syncthreads();
    for (int off = 128; off > 0; off >>= 1) {
        if (tid < off) red[tid] += red[tid + off];
        __syncthreads();
    }
    float sd = sqrtf(red[0] / (float)(D - 1));
    out[2 * N + tid] = c / (sd + 1e-6f);
}

// ---------------------------------------------------------------------------
extern "C" void kernel_launch(void* const* d_in, const int* in_sizes, int n_in,
                              void* d_out, int out_size) {
    const float* E    = (const float*)d_in[0];
    const float* Dx   = (const float*)d_in[1];
    const float* Dy   = (const float*)d_in[2];
    const float* temb = (const float*)d_in[3];
    const int*   toks = (const int*)d_in[4];
    float* out = (float*)d_out;

    const int SM1 = 73728;   // 4 x [128][36w] tiles; epilogue Xs+sx+tot fits
    const int SM2 = 208896;  // cV hi/lo [256][68w] + XT hi/lo [128][68w]
    static int inited = 0;
    static cudaStream_t s2;
    static cudaEvent_t ev1, ev2;
    if (!inited) {
        cudaFuncSetAttribute(k_gemm1, cudaFuncAttributeMaxDynamicSharedMemorySize, SM1);
        cudaFuncSetAttribute(k_gemm2, cudaFuncAttributeMaxDynamicSharedMemorySize, SM2);
        cudaStreamCreateWithFlags(&s2, cudaStreamNonBlocking);
        cudaEventCreateWithFlags(&ev1, cudaEventDisableTiming);
        cudaEventCreateWithFlags(&ev2, cudaEventDisableTiming);
        inited = 1;
    }

    k_gather_prep<<<T, 256>>>(temb, toks);
    k_prep_cv<<<D, 64>>>();
    k_gemm1<<<N / 128, 256, SM1>>>(Dx, out);

    // fork: gemm2 (rho) runs concurrently with the astar->y->u->vstar chain
    cudaEventRecord(ev1, 0);
    cudaStreamWaitEvent(s2, ev1, 0);
    k_gemm2<<<N / 128, 512, SM2, s2>>>(out);
    cudaEventRecord(ev2, s2);

    k_astar_ln<<<1, D>>>();
    k_y<<<N / 8, 256>>>(Dy, out);
    k_u<<<D, 256>>>(E, out);
    k_vstar<<<1, D>>>(out);

    cudaStreamWaitEvent(0, ev2, 0);  // join
}

// round 6
// speedup vs baseline: 2.5575x; 1.0138x over previous
#include <cuda_runtime.h>
#include <cuda_bf16.h>
#include <math.h>

#define N 16384
#define D 256
#define T 128

typedef unsigned int u32;
typedef unsigned long long u64;

// ---------------- scratch ---------------------------------------------------
__device__ float g_V[T * D];        // gathered token embeddings fp32 [t][d]
__device__ u32   g_Vh[T * 128];     // V hi split bf16x2 [t][k/2]
__device__ u32   g_Vl[T * 128];     // V lo split
__device__ u32   g_XTh[N * 64];     // X^T hi split, bf16x2 [n][t/2]
__device__ u32   g_XTl[N * 64];     // X^T lo split
__device__ u32   g_cVh[D * 64];     // (0.97^(T-s)*V[s][d]) hi split, [d][s/2]
__device__ u32   g_cVl[D * 64];
__device__ float g_part2[128 * T];  // dot partials [block][s]
__device__ float g_lnA[D];
__device__ float g_u[D];

// ---------------- helpers ----------------------------------------------------
__device__ __forceinline__ u32 s2u(const void* p) {
    u32 a;
    asm("{ .reg .u64 t; cvta.to.shared.u64 t, %1; cvt.u32.u64 %0, t; }" : "=r"(a) : "l"(p));
    return a;
}
__device__ __forceinline__ u32 pack_bf16(float lo, float hi) {
    u32 r;
    asm("cvt.rn.bf16x2.f32 %0, %1, %2;" : "=r"(r) : "f"(hi), "f"(lo));
    return r;
}

#define LDSM_X4(r, addr)                                                        \
    asm volatile(                                                               \
        "ldmatrix.sync.aligned.m8n8.x4.shared.b16 {%0,%1,%2,%3}, [%4];"         \
        : "=r"((r)[0]), "=r"((r)[1]), "=r"((r)[2]), "=r"((r)[3])                \
        : "r"(addr))

__device__ __forceinline__ void mma16816(float* c, const u32* a, u32 b0, u32 b1) {
    asm volatile(
        "mma.sync.aligned.m16n8k16.row.col.f32.bf16.bf16.f32 "
        "{%0,%1,%2,%3}, {%4,%5,%6,%7}, {%8,%9}, {%0,%1,%2,%3};"
        : "+f"(c[0]), "+f"(c[1]), "+f"(c[2]), "+f"(c[3])
        : "r"(a[0]), "r"(a[1]), "r"(a[2]), "r"(a[3]), "r"(b0), "r"(b1));
}

// split float4 -> hi u64 (2 bf16x2) + lo u64
__device__ __forceinline__ void split4(float4 v, u64& hp, u64& lp) {
    u32 h0 = pack_bf16(v.x, v.y);
    u32 h1 = pack_bf16(v.z, v.w);
    u32 l0 = pack_bf16(v.x - __uint_as_float(h0 << 16),
                       v.y - __uint_as_float(h0 & 0xFFFF0000u));
    u32 l1 = pack_bf16(v.z - __uint_as_float(h1 << 16),
                       v.w - __uint_as_float(h1 & 0xFFFF0000u));
    hp = ((u64)h1 << 32) | h0;
    lp = ((u64)l1 << 32) | l0;
}

// ---------------- K1: gather + V splits --------------------------------------
__global__ __launch_bounds__(256) void k_gather_prep(const float* __restrict__ temb,
                                                     const int* __restrict__ toks) {
    int t = blockIdx.x, tid = threadIdx.x;
    g_V[t * D + tid] = temb[(size_t)toks[t] * D + tid];
    __syncthreads();
    if (tid < 128) {
        float v0 = g_V[t * D + 2 * tid];
        float v1 = g_V[t * D + 2 * tid + 1];
        u32 h = pack_bf16(v0, v1);
        u32 l = pack_bf16(v0 - __uint_as_float(h << 16),
                          v1 - __uint_as_float(h & 0xFFFF0000u));
        g_Vh[t * 128 + tid] = h;
        g_Vl[t * 128 + tid] = l;
    }
}

// ---------------- K2: cV splits ----------------------------------------------
__global__ void k_prep_cv() {
    int d = blockIdx.x;
    int s2 = threadIdx.x;  // 64 threads: s pair
    int s0 = 2 * s2, s1 = s0 + 1;
    float c0 = (float)pow(0.97, (double)(T - s0));
    float c1 = (float)pow(0.97, (double)(T - s1));
    float a0 = c0 * g_V[s0 * D + d];
    float a1 = c1 * g_V[s1 * D + d];
    u32 h = pack_bf16(a0, a1);
    u32 l = pack_bf16(a0 - __uint_as_float(h << 16), a1 - __uint_as_float(h & 0xFFFF0000u));
    g_cVh[d * 64 + s2] = h;
    g_cVl[d * 64 + s2] = l;
}

// ---------------- K3: GEMM1 (mma.sync, 32x64 warp tiles, Dx prefetch) --------
// C[n][t] = sum_k Dx[n][k]*V[t][k]; epilogue: relu+cumsum, XT splits, partials.
#define PA1 36  // word pitch for [128][32w] tiles
__global__ __launch_bounds__(256) void k_gemm1(const float* __restrict__ Dx,
                                               float* __restrict__ out) {
    extern __shared__ char sm[];
    const int S_AH = 0, S_AL = 18432, S_BH = 36864, S_BL = 55296;
    int tid = threadIdx.x;
    int lane = tid & 31, wid = tid >> 5;
    int gr = lane >> 2, gc = lane & 3;
    int r8 = lane & 7, sub = lane >> 3;
    int m0w = (wid & 3) * 32;   // n rows
    int t0 = (wid >> 2) * 64;   // t cols
    int n0 = blockIdx.x * 128;
    u32 smb = s2u(sm);

    float acc[2][8][4];
#pragma unroll
    for (int i = 0; i < 2; i++)
#pragma unroll
        for (int j = 0; j < 8; j++)
#pragma unroll
            for (int q = 0; q < 4; q++) acc[i][j][q] = 0.f;

    // prefetch chunk 0 of Dx
    float4 pa[8];
#pragma unroll
    for (int r = 0; r < 8; r++) {
        int gi = tid + 256 * r;
        int row = gi >> 4, f4 = gi & 15;
        pa[r] = *(const float4*)&Dx[(size_t)(n0 + row) * D + f4 * 4];
    }

    for (int c = 0; c < 4; c++) {  // K chunks of 64
#pragma unroll
        for (int r = 0; r < 8; r++) {
            int gi = tid + 256 * r;
            int row = gi >> 4, f4 = gi & 15;
            u64 hp, lp;
            split4(pa[r], hp, lp);
            *(u64*)(sm + S_AH + row * (PA1 * 4) + f4 * 8) = hp;
            *(u64*)(sm + S_AL + row * (PA1 * 4) + f4 * 8) = lp;
        }
#pragma unroll
        for (int r = 0; r < 4; r++) {
            int gi = tid + 256 * r;  // 1024 uint4 per split
            int row = gi >> 3, j4 = gi & 7;
            *(uint4*)(sm + S_BH + row * (PA1 * 4) + j4 * 16) =
                ((const uint4*)g_Vh)[row * 32 + c * 8 + j4];
            *(uint4*)(sm + S_BL + row * (PA1 * 4) + j4 * 16) =
                ((const uint4*)g_Vl)[row * 32 + c * 8 + j4];
        }
        __syncthreads();
        if (c < 3) {
#pragma unroll
            for (int r = 0; r < 8; r++) {
                int gi = tid + 256 * r;
                int row = gi >> 4, f4 = gi & 15;
                pa[r] = *(const float4*)&Dx[(size_t)(n0 + row) * D + (c + 1) * 64 + f4 * 4];
            }
        }
#pragma unroll
        for (int ks = 0; ks < 4; ks++) {
            u32 ah[2][4], al[2][4];
#pragma unroll
            for (int mt = 0; mt < 2; mt++) {
                int aw = (m0w + mt * 16 + r8 + (sub & 1) * 8) * PA1 + (sub >> 1) * 4 + ks * 8;
                LDSM_X4(ah[mt], smb + S_AH + aw * 4);
                LDSM_X4(al[mt], smb + S_AL + aw * 4);
            }
#pragma unroll
            for (int g = 0; g < 4; g++) {
                u32 bh[4], bl[4];
                int bw = (t0 + g * 16 + r8 + (sub >> 1) * 8) * PA1 + (sub & 1) * 4 + ks * 8;
                LDSM_X4(bh, smb + S_BH + bw * 4);
                LDSM_X4(bl, smb + S_BL + bw * 4);
#pragma unroll
                for (int mt = 0; mt < 2; mt++) {
                    mma16816(acc[mt][2 * g], ah[mt], bh[0], bh[1]);
                    mma16816(acc[mt][2 * g + 1], ah[mt], bh[2], bh[3]);
                    mma16816(acc[mt][2 * g], ah[mt], bl[0], bl[1]);
                    mma16816(acc[mt][2 * g + 1], ah[mt], bl[2], bl[3]);
                    mma16816(acc[mt][2 * g], al[mt], bh[0], bh[1]);
                    mma16816(acc[mt][2 * g + 1], al[mt], bh[2], bh[3]);
                }
            }
        }
        __syncthreads();
    }

    // ---- epilogue: relu -> Xs[128][130], 2-phase cumsum, splits, partials ----
    float* Xs = (float*)sm;
    float* sx = (float*)(sm + 66560);           // [128] x_f
    float* tot = (float*)(sm + 66560 + 512);    // [128][2] half totals
#pragma unroll
    for (int mt = 0; mt < 2; mt++)
#pragma unroll
        for (int j = 0; j < 8; j++) {
            int row = m0w + mt * 16 + gr;
            int col = t0 + j * 8 + 2 * gc;
            *(float2*)&Xs[row * 130 + col] =
                make_float2(fmaxf(acc[mt][j][0], 0.f), fmaxf(acc[mt][j][1], 0.f));
            *(float2*)&Xs[(row + 8) * 130 + col] =
                make_float2(fmaxf(acc[mt][j][2], 0.f), fmaxf(acc[mt][j][3], 0.f));
        }
    __syncthreads();
    {
        int n = tid & 127, h = tid >> 7;
        float v[64];
        float a = 0.f;
#pragma unroll
        for (int i = 0; i < 32; i++) {
            float2 p = *(float2*)&Xs[n * 130 + h * 64 + 2 * i];
            a += p.x;
            v[2 * i] = a;
            a += p.y;
            v[2 * i + 1] = a;
        }
        tot[n * 2 + h] = a;
        __syncthreads();
        float off = h ? tot[n * 2] : 0.f;
#pragma unroll
        for (int i = 0; i < 64; i++) v[i] += off;
#pragma unroll
        for (int p = 0; p < 32; p++) {
            float x0 = v[2 * p], x1 = v[2 * p + 1];
            *(float2*)&Xs[n * 130 + h * 64 + 2 * p] = make_float2(x0, x1);
            u32 hh = pack_bf16(x0, x1);
            u32 ll = pack_bf16(x0 - __uint_as_float(hh << 16),
                               x1 - __uint_as_float(hh & 0xFFFF0000u));
            g_XTh[(size_t)(n0 + n) * 64 + h * 32 + p] = hh;
            g_XTl[(size_t)(n0 + n) * 64 + h * 32 + p] = ll;
        }
        if (h == 1) {
            out[n0 + n] = v[63];
            sx[n] = v[63];
        }
    }
    __syncthreads();
    {
        int t = tid & 127, h = tid >> 7;
        float s = 0.f;
        for (int n2 = h * 64; n2 < h * 64 + 64; n2++)
            s = fmaf(Xs[n2 * 130 + t], sx[n2], s);
        tot[t * 2 + h] = s;
    }
    __syncthreads();
    if (tid < 128) g_part2[blockIdx.x * 128 + tid] = tot[tid * 2] + tot[tid * 2 + 1];
}

// ---------------- K4: GEMM2 (mma.sync, 32x64 warp tiles) ---------------------
// C[d][n] = sum_s cV[d][s]*XT[n][s]; coalesced float2 stores to rho[d][n].
#define PA2 68  // word pitch for [*][64w] tiles
__global__ __launch_bounds__(512) void k_gemm2(float* __restrict__ out) {
    extern __shared__ char sm[];
    const int S_AH = 0, S_AL = 69632, S_BH = 139264, S_BL = 174080;
    int tid = threadIdx.x;
    int lane = tid & 31, wid = tid >> 5;  // wid 0..15
    int gr = lane >> 2, gc = lane & 3;
    int r8 = lane & 7, sub = lane >> 3;
    int m0w = (wid & 7) * 32;   // d rows
    int nb = (wid >> 3) * 64;   // n cols within tile
    int n0 = blockIdx.x * 128;
    u32 smb = s2u(sm);

#pragma unroll
    for (int r = 0; r < 8; r++) {
        int gi = tid + 512 * r;  // 4096 uint4
        int row = gi >> 4, j4 = gi & 15;
        *(uint4*)(sm + S_AH + row * (PA2 * 4) + j4 * 16) =
            ((const uint4*)g_cVh)[row * 16 + j4];
        *(uint4*)(sm + S_AL + row * (PA2 * 4) + j4 * 16) =
            ((const uint4*)g_cVl)[row * 16 + j4];
    }
#pragma unroll
    for (int r = 0; r < 4; r++) {
        int gi = tid + 512 * r;  // 2048 uint4
        int row = gi >> 4, j4 = gi & 15;
        *(uint4*)(sm + S_BH + row * (PA2 * 4) + j4 * 16) =
            ((const uint4*)g_XTh)[(size_t)(n0 + row) * 16 + j4];
        *(uint4*)(sm + S_BL + row * (PA2 * 4) + j4 * 16) =
            ((const uint4*)g_XTl)[(size_t)(n0 + row) * 16 + j4];
    }
    __syncthreads();

    float acc[2][8][4];
#pragma unroll
    for (int i = 0; i < 2; i++)
#pragma unroll
        for (int j = 0; j < 8; j++)
#pragma unroll
            for (int q = 0; q < 4; q++) acc[i][j][q] = 0.f;

#pragma unroll
    for (int ks = 0; ks < 8; ks++) {
        u32 ah[2][4], al[2][4];
#pragma unroll
        for (int mt = 0; mt < 2; mt++) {
            int aw = (m0w + mt * 16 + r8 + (sub & 1) * 8) * PA2 + (sub >> 1) * 4 + ks * 8;
            LDSM_X4(ah[mt], smb + S_AH + aw * 4);
            LDSM_X4(al[mt], smb + S_AL + aw * 4);
        }
#pragma unroll
        for (int g = 0; g < 4; g++) {
            u32 bh[4], bl[4];
            int bw = (nb + g * 16 + r8 + (sub >> 1) * 8) * PA2 + (sub & 1) * 4 + ks * 8;
            LDSM_X4(bh, smb + S_BH + bw * 4);
            LDSM_X4(bl, smb + S_BL + bw * 4);
#pragma unroll
            for (int mt = 0; mt < 2; mt++) {
                mma16816(acc[mt][2 * g], ah[mt], bh[0], bh[1]);
                mma16816(acc[mt][2 * g + 1], ah[mt], bh[2], bh[3]);
                mma16816(acc[mt][2 * g], ah[mt], bl[0], bl[1]);
                mma16816(acc[mt][2 * g + 1], ah[mt], bl[2], bl[3]);
                mma16816(acc[mt][2 * g], al[mt], bh[0], bh[1]);
                mma16816(acc[mt][2 * g + 1], al[mt], bh[2], bh[3]);
            }
        }
    }

    float* rho = out + 2 * N + D;
#pragma unroll
    for (int mt = 0; mt < 2; mt++)
#pragma unroll
        for (int j = 0; j < 8; j++) {
            int d = m0w + mt * 16 + gr;
            int col = n0 + nb + j * 8 + 2 * gc;
            *(float2*)&rho[(size_t)d * N + col] = make_float2(acc[mt][j][0], acc[mt][j][1]);
            *(float2*)&rho[(size_t)(d + 8) * N + col] = make_float2(acc[mt][j][2], acc[mt][j][3]);
        }
}

// ---------------- K5: a*[d] -> layernorm -> g_lnA ----------------------------
__global__ void k_astar_ln() {
    __shared__ float gg[T];
    __shared__ float red[256];
    int tid = threadIdx.x;  // = d
    if (tid < T) {
        float s = 0.f;
        for (int b = 0; b < 128; b++) s += g_part2[b * 128 + tid];
        gg[tid] = (tid < T - 1) ? (float)pow(0.97, (double)(T - 1 - tid)) * s : 0.f;
    }
    __syncthreads();
    float a = 0.f;
    for (int s = 0; s < T - 1; s++) a = fmaf(gg[s], g_V[s * D + tid], a);
    red[tid] = a;
    __syncthreads();
    for (int off = 128; off > 0; off >>= 1) {
        if (tid < off) red[tid] += red[tid + off];
        __syncthreads();
    }
    float m = red[0] * (1.f / D);
    __syncthreads();
    float ctr = a - m;
    red[tid] = ctr * ctr;
    __syncthreads();
    for (int off = 128; off > 0; off >>= 1) {
        if (tid < off) red[tid] += red[tid + off];
        __syncthreads();
    }
    float sd = sqrtf(red[0] / (float)(D - 1));
    g_lnA[tid] = ctr / (sd + 1e-6f);
}

// ---------------- K6: y[n] = relu(Dy.lnA) * relu(x_f) -> out[N:2N) ----------
__global__ void k_y(const float* __restrict__ Dy, float* __restrict__ out) {
    __shared__ float sa[D];
    int tid = threadIdx.x;
    sa[tid] = g_lnA[tid];
    __syncthreads();
    int warp = tid >> 5, lane = tid & 31;
    int n = blockIdx.x * 8 + warp;
    const float4* row = (const float4*)&Dy[(size_t)n * D];
    float s = 0.f;
#pragma unroll
    for (int r = 0; r < 2; r++) {
        float4 v = row[lane + 32 * r];
        int d = 4 * (lane + 32 * r);
        s = fmaf(v.x, sa[d], s);
        s = fmaf(v.y, sa[d + 1], s);
        s = fmaf(v.z, sa[d + 2], s);
        s = fmaf(v.w, sa[d + 3], s);
    }
#pragma unroll
    for (int off = 16; off > 0; off >>= 1) s += __shfl_down_sync(0xffffffffu, s, off);
    if (lane == 0) out[N + n] = fmaxf(s, 0.f) * fmaxf(out[n], 0.f);
}

// ---------------- K7: u[d] = E[d,:].y ---------------------------------------
__global__ void k_u(const float* __restrict__ E, const float* __restrict__ out) {
    __shared__ float red[256];
    int d = blockIdx.x, tid = threadIdx.x;
    const float4* e = (const float4*)&E[(size_t)d * N];
    const float4* y = (const float4*)&out[N];
    float s = 0.f;
#pragma unroll 4
    for (int r = 0; r < 16; r++) {
        float4 a = e[tid + 256 * r];
        float4 b = y[tid + 256 * r];
        s = fmaf(a.x, b.x, s);
        s = fmaf(a.y, b.y, s);
        s = fmaf(a.z, b.z, s);
        s = fmaf(a.w, b.w, s);
    }
    red[tid] = s;
    __syncthreads();
    for (int off = 128; off > 0; off >>= 1) {
        if (tid < off) red[tid] += red[tid + off];
        __syncthreads();
    }
    if (tid == 0) g_u[d] = red[0];
}

// ---------------- K8: v* = layernorm(u) -> out[2N:2N+D) ---------------------
__global__ void k_vstar(float* __restrict__ out) {
    __shared__ float red[256];
    int tid = threadIdx.x;
    float a = g_u[tid];
    red[tid] = a;
    __syncthreads();
    for (int off = 128; off > 0; off >>= 1) {
        if (tid < off) red[tid] += red[tid + off];
        __syncthreads();
    }
    float m = red[0] * (1.f / D);
    __syncthreads();
    float c = a - m;
    red[tid] = c * c;
    __syncthreads();
    for (int off = 128; off > 0; off >>= 1) {
        if (tid < off) red[tid] += red[tid + off];
        __syncthreads();
    }
    float sd = sqrtf(red[0] / (float)(D - 1));
    out[2 * N + tid] = c / (sd + 1e-6f);
}

// ---------------------------------------------------------------------------
extern "C" void kernel_launch(void* const* d_in, const int* in_sizes, int n_in,
                              void* d_out, int out_size) {
    const float* E    = (const float*)d_in[0];
    const float* Dx   = (const float*)d_in[1];
    const float* Dy   = (const float*)d_in[2];
    const float* temb = (const float*)d_in[3];
    const int*   toks = (const int*)d_in[4];
    float* out = (float*)d_out;

    const int SM1 = 73728;   // 4 x [128][36w] tiles; epilogue Xs+sx+tot fits
    const int SM2 = 208896;  // cV hi/lo [256][68w] + XT hi/lo [128][68w]
    static int inited = 0;
    static cudaStream_t s2;
    static cudaEvent_t evG, ev1, ev2;
    if (!inited) {
        cudaFuncSetAttribute(k_gemm1, cudaFuncAttributeMaxDynamicSharedMemorySize, SM1);
        cudaFuncSetAttribute(k_gemm2, cudaFuncAttributeMaxDynamicSharedMemorySize, SM2);
        cudaStreamCreateWithFlags(&s2, cudaStreamNonBlocking);
        cudaEventCreateWithFlags(&evG, cudaEventDisableTiming);
        cudaEventCreateWithFlags(&ev1, cudaEventDisableTiming);
        cudaEventCreateWithFlags(&ev2, cudaEventDisableTiming);
        inited = 1;
    }

    k_gather_prep<<<T, 256>>>(temb, toks);
    cudaEventRecord(evG, 0);
    cudaStreamWaitEvent(s2, evG, 0);
    k_prep_cv<<<D, 64, 0, s2>>>();  // overlaps with gemm1

    k_gemm1<<<N / 128, 256, SM1>>>(Dx, out);

    // fork: gemm2 (rho) runs concurrently with the astar->y->u->vstar chain
    cudaEventRecord(ev1, 0);
    cudaStreamWaitEvent(s2, ev1, 0);
    k_gemm2<<<N / 128, 512, SM2, s2>>>(out);
    cudaEventRecord(ev2, s2);

    k_astar_ln<<<1, D>>>();
    k_y<<<N / 8, 256>>>(Dy, out);
    k_u<<<D, 256>>>(E, out);
    k_vstar<<<1, D>>>(out);

    cudaStreamWaitEvent(0, ev2, 0);  // join
}